// round 10
// baseline (speedup 1.0000x reference)
#include <cuda_runtime.h>
#include <math.h>

// Global scratch (no cudaMalloc allowed)
__device__ float g_part[320];   // per-warp partials: [b*16 + wrp*2 + hi]
__device__ unsigned g_done = 0; // warp-arrival counter (self-resetting)

#define NB 20
#define NT 256
#define NWARPS_TOTAL (NB * 8)
#define PITCH 61                // Tsh row pitch (odd -> conflict-free strided access)

__device__ __forceinline__ float fast_sigmoid(float a) {
    return 1.f / (1.f + __expf(-a));
}
__device__ __forceinline__ float fast_tanh(float a) {
    float e = __expf(2.f * a);
    return (e - 1.f) / (e + 1.f);
}
__device__ __forceinline__ void bar_sew() {   // named barrier: SE group = threads 0..127
    asm volatile("bar.sync 1, 128;" ::: "memory");
}

__global__ void __launch_bounds__(NT, 1)
cnn_fused(const float* __restrict__ x,
          const float* __restrict__ se_w1,
          const float* __restrict__ se_b1,
          const float* __restrict__ se_w2,
          const float* __restrict__ se_b2,
          const float* __restrict__ conv_w,
          const float* __restrict__ conv_b,
          const float* __restrict__ fcn_w1,
          const float* __restrict__ fcn_b1,
          const float* __restrict__ fcn_w2,
          const float* __restrict__ fcn_b2,
          float* __restrict__ out) {
    const int t = threadIdx.x;
    const int b = blockIdx.x;
    const int o = b >> 1;            // output channel 0..9
    const int q = b & 1;             // wi half: global wi in [q*60, q*60+60)
    const int lane = t & 31;
    const int wrp = t >> 5;

    __shared__ float Tsh[64 * PITCH + 64];  // T[kh][wi_local(60)], pitch 61, padded
    __shared__ float w2sh[64 * 65];         // se_w2 rows, pitch 65 (conflict-free)
    __shared__ float invn[64];
    __shared__ float scalsh[4];             // dot0a, dot0b, sumsq_wa, sumsq_wb
    __shared__ float hsh[128];
    __shared__ float ssh[128];
    __shared__ float sewsh[128];            // interleaved [kh*2 + hi]
    __shared__ float fw1sh[200];            // FCN tail staged in smem (pre-join)
    __shared__ float fb1sh[10];
    __shared__ float fw2sh[20];
    __shared__ float fb2sh[2];
    __shared__ float ymsh[20];
    __shared__ float h2sh[10];

    const float cb = __ldg(&conv_b[o]);

    if (t < 128) {
        // =============== SE path (warps 0-3, named barriers) ===============
        const int j = t >> 1, p = t & 1;    // GEMV1 mapping: 2 threads per row j

        // S0a: prefetch se_w1 row-half into registers + bias scalars.
        float w1r[32];
        {
            const float4* w1p = (const float4*)(se_w1 + j * 64 + p * 32);
#pragma unroll
            for (int i = 0; i < 8; i++) {
                float4 v = w1p[i];
                w1r[4 * i] = v.x; w1r[4 * i + 1] = v.y;
                w1r[4 * i + 2] = v.z; w1r[4 * i + 3] = v.w;
            }
        }
        const float b1v = __ldg(&se_b1[j]);        // for merged S2/S3
        const float b2v = __ldg(&se_b2[t & 63]);   // for S4

        // S0b: stage se_w2 row-half into pitched smem.
        {
            const float4* w2p = (const float4*)(se_w2 + j * 64 + p * 32);
            float* dst = w2sh + j * 65 + p * 32;
#pragma unroll
            for (int i = 0; i < 8; i++) {
                float4 v = w2p[i];
                dst[4 * i] = v.x; dst[4 * i + 1] = v.y;
                dst[4 * i + 2] = v.z; dst[4 * i + 3] = v.w;
            }
        }
        // S0c: stage FCN tail params into smem (rides the same DRAM trip;
        // visible to ALL warps after the join __syncthreads below).
        for (int i = t; i < 200; i += 128) fw1sh[i] = fcn_w1[i];
        if (t < 10)       fb1sh[t]      = fcn_b1[t];
        else if (t < 30)  fw2sh[t - 10] = fcn_w2[t - 10];
        else if (t < 32)  fb2sh[t - 30] = fcn_b2[t - 30];

        // S1: norms (t<64, 1 thr/channel) | wav scalars (t in [64,128), 16 thr/scalar)
        if (t < 64) {
            const float4* e = (const float4*)(x + (t + 1) * 128);
            float a0 = 0.f, a1 = 0.f, a2 = 0.f, a3 = 0.f;
#pragma unroll
            for (int i = 0; i < 32; i++) {
                float4 v = e[i];
                a0 = fmaf(v.x, v.x, a0); a1 = fmaf(v.y, v.y, a1);
                a2 = fmaf(v.z, v.z, a2); a3 = fmaf(v.w, v.w, a3);
            }
            invn[t] = rsqrtf((a0 + a1) + (a2 + a3));
        } else {
            int ts = t - 64;                // 0..63 (whole warps 2,3)
            int which = ts >> 4;            // 0: e0.wa, 1: e0.wb, 2: |wa|^2, 3: |wb|^2
            int sl = ts & 15;               // 16 threads per scalar, 8 elems each
            const float4* e0 = (const float4*)(x + 128 + sl * 8);
            const float4* wv = (const float4*)(x + ((which & 1) ? 65 * 128 : 0) + sl * 8);
            float a0 = 0.f, a1 = 0.f;
            if (which < 2) {
#pragma unroll
                for (int i = 0; i < 2; i++) {
                    float4 u = e0[i], v = wv[i];
                    a0 = fmaf(u.x, v.x, a0); a1 = fmaf(u.y, v.y, a1);
                    a0 = fmaf(u.z, v.z, a0); a1 = fmaf(u.w, v.w, a1);
                }
            } else {
#pragma unroll
                for (int i = 0; i < 2; i++) {
                    float4 v = wv[i];
                    a0 = fmaf(v.x, v.x, a0); a1 = fmaf(v.y, v.y, a1);
                    a0 = fmaf(v.z, v.z, a0); a1 = fmaf(v.w, v.w, a1);
                }
            }
            float a = a0 + a1;                       // whole warps 2,3: uniform shfls
            a += __shfl_xor_sync(0xffffffffu, a, 1);
            a += __shfl_xor_sync(0xffffffffu, a, 2);
            a += __shfl_xor_sync(0xffffffffu, a, 4);
            a += __shfl_xor_sync(0xffffffffu, a, 8);
            if (sl == 0) scalsh[which] = a;
        }
        bar_sew();

        // S2+S3 merged: u[j] = w1row . invn; then h[r][j] = tanh(c_r*u[j] + b1[j]).
        // Reference quirk: numerator = channel-0 dot only (jnp.diagonal of (64,1)),
        // so eegr[r][j] = dot0_r/(|e_j||wav_r|) and GEMV1 factorizes through u[j].
        {
            float a0 = 0.f, a1 = 0.f;
#pragma unroll
            for (int i = 0; i < 16; i++) {
                a0 = fmaf(w1r[2 * i],     invn[p * 32 + 2 * i],     a0);
                a1 = fmaf(w1r[2 * i + 1], invn[p * 32 + 2 * i + 1], a1);
            }
            float a = a0 + a1;
            a += __shfl_xor_sync(0xffffffffu, a, 1);   // whole warps 0-3
            float c0 = scalsh[0] * rsqrtf(scalsh[2]);
            float c1 = scalsh[1] * rsqrtf(scalsh[3]);
            if (p == 0) {
                hsh[j]      = fast_tanh(fmaf(c0, a, b1v));
                hsh[64 + j] = fast_tanh(fmaf(c1, a, b1v));
            }
        }
        bar_sew();

        // S4: GEMV2 + sigmoid — 1 thread per output (r,j), 64-deep dot from w2sh.
        {
            int r = t >> 6, jj = t & 63;
            const float* w = w2sh + jj * 65;
            const float* hr = hsh + r * 64;
            float a0 = 0.f, a1 = 0.f, a2 = 0.f, a3 = 0.f;
#pragma unroll
            for (int i = 0; i < 16; i++) {
                a0 = fmaf(w[4 * i],     hr[4 * i],     a0);
                a1 = fmaf(w[4 * i + 1], hr[4 * i + 1], a1);
                a2 = fmaf(w[4 * i + 2], hr[4 * i + 2], a2);
                a3 = fmaf(w[4 * i + 3], hr[4 * i + 3], a3);
            }
            ssh[t] = fast_sigmoid(((a0 + a1) + (a2 + a3)) + b2v);
        }
        bar_sew();

        // S5: row softmax over 64 (warp r -> row r), interleaved output.
        if (wrp < 2) {
            float v0 = ssh[wrp * 64 + lane];
            float v1 = ssh[wrp * 64 + 32 + lane];
            float m = fmaxf(v0, v1);
#pragma unroll
            for (int s = 16; s >= 1; s >>= 1) m = fmaxf(m, __shfl_xor_sync(0xffffffffu, m, s));
            float e0 = __expf(v0 - m), e1 = __expf(v1 - m);
            float su = e0 + e1;
#pragma unroll
            for (int s = 16; s >= 1; s >>= 1) su += __shfl_xor_sync(0xffffffffu, su, s);
            float inv = 1.f / su;
            sewsh[lane * 2 + wrp] = e0 * inv;
            sewsh[(lane + 32) * 2 + wrp] = e1 * inv;
        }
    } else {
        // =============== Stage A (warps 4-7): T tile, 30 wi per thread ===============
        int ts = t - 128;
        int row = ts >> 1, h = ts & 1;
        const float* wp = conv_w + (o * 64 + row) * 9;
        float wr[9];
#pragma unroll
        for (int i = 0; i < 9; i++) wr[i] = wp[i];
#pragma unroll
        for (int c = 0; c < 2; c++) {
            int wi0 = h * 30 + c * 15;                    // local wi base
            const float* e = x + (row + 1) * 128 + q * 60 + wi0;
            float win[23];
#pragma unroll
            for (int i = 0; i < 23; i++) win[i] = e[i];
            float* Trow = Tsh + row * PITCH + wi0;
#pragma unroll
            for (int jj = 0; jj < 15; jj++) {
                float s = 0.f;
#pragma unroll
                for (int k = 0; k < 9; k++) s = fmaf(win[jj + k], wr[k], s);
                Trow[jj] = s;
            }
        }
    }
    __syncthreads();   // join SE + stage A (also makes fcn smem staging block-visible)

    // =============== Combine: 120 outputs x 2 threads; warp-uniform shuffles ===============
    // oid = t>>1 (wi = oid>>1 local, hi = oid&1), kq = t&1, kh = kq + 2*i.
    // t >= 240: oid in [120,128) -> in-bounds garbage (Tsh padded); masked below.
    float v;
    {
        int oid = t >> 1, kq = t & 1;
        int wi = oid >> 1, hi = oid & 1;
        const float* Tc = Tsh + kq * PITCH + wi;
        const float* wsp = sewsh + kq * 2 + hi;
        float p0 = 0.f, p1 = 0.f;
#pragma unroll
        for (int i = 0; i < 32; i += 2) {
            p0 = fmaf(wsp[4 * i],       Tc[2 * i * PITCH],       p0);
            p1 = fmaf(wsp[4 * (i + 1)], Tc[2 * (i + 1) * PITCH], p1);
        }
        float pp = p0 + p1;
        pp += __shfl_xor_sync(0xffffffffu, pp, 1);     // sum kq halves
        v = 0.f;
        if (t < 240) v = fmaxf(pp + cb, 0.f);
        // Sum over wi (lane bits 2,3,4), keeping bits 0,1 fixed (bit1 = hi).
        v += __shfl_xor_sync(0xffffffffu, v, 4);
        v += __shfl_xor_sync(0xffffffffu, v, 8);
        v += __shfl_xor_sync(0xffffffffu, v, 16);
        // lane 0 holds hi=0 partial, lane 2 holds hi=1 partial (over this warp's 8 wi)
    }

    // =============== Per-warp arrival: distinct slots + acq_rel counter ===============
    float v2 = __shfl_sync(0xffffffffu, v, 2);         // hi=1 partial -> lane 0
    unsigned old = 0u;
    if (lane == 0) {
        float* gp = g_part + b * 16 + wrp * 2;
        gp[0] = v;                                      // relaxed stores, ordered by the
        gp[1] = v2;                                     // release below (same thread)
        asm volatile("atom.add.acq_rel.gpu.u32 %0, [%1], %2;"
                     : "=r"(old) : "l"(&g_done), "r"(1u) : "memory");
    }
    old = __shfl_sync(0xffffffffu, old, 0);             // warp-uniform broadcast

    // =============== Finisher: the last-arriving warp runs the FCN tail ===============
    if (old == NWARPS_TOTAL - 1) {
        __syncwarp();                                   // extend lane0's acquire to the warp
        if (lane < 20) {
            int oo = lane >> 1, hh = lane & 1;
            float s = 0.f;
#pragma unroll
            for (int qq = 0; qq < 2; qq++)
#pragma unroll
                for (int w = 0; w < 8; w++)
                    s += __ldcg(&g_part[(oo * 2 + qq) * 16 + w * 2 + hh]);
            ymsh[lane] = s * (1.f / 120.f);
        }
        __syncwarp();
        if (lane < 10) {
            float a = fb1sh[lane];
            const float* w = fw1sh + lane * 20;
#pragma unroll
            for (int k = 0; k < 20; k++) a = fmaf(ymsh[k], w[k], a);
            h2sh[lane] = fast_sigmoid(a);
        }
        __syncwarp();
        // All 32 lanes compute a logit redundantly (r2 = lane&1) -> uniform shfl.
        {
            int r2 = lane & 1;
            float l = fb2sh[r2];
#pragma unroll
            for (int jj = 0; jj < 10; jj++) l = fmaf(h2sh[jj], fw2sh[r2 * 10 + jj], l);
            float lo = __shfl_xor_sync(0xffffffffu, l, 1);
            if (lane == 0) {
                float m = fmaxf(l, lo);
                float e0 = __expf(l - m), e1 = __expf(lo - m);
                float inv = 1.f / (e0 + e1);
                out[0] = e0 * inv;
                out[1] = e1 * inv;
                g_done = 0u;                            // replay-safe reset (all arrived)
            }
        }
    }
}

extern "C" void kernel_launch(void* const* d_in, const int* in_sizes, int n_in,
                              void* d_out, int out_size) {
    const float* x      = (const float*)d_in[0];
    const float* se_w1  = (const float*)d_in[1];
    const float* se_b1  = (const float*)d_in[2];
    const float* se_w2  = (const float*)d_in[3];
    const float* se_b2  = (const float*)d_in[4];
    const float* conv_w = (const float*)d_in[5];
    const float* conv_b = (const float*)d_in[6];
    const float* fcn_w1 = (const float*)d_in[7];
    const float* fcn_b1 = (const float*)d_in[8];
    const float* fcn_w2 = (const float*)d_in[9];
    const float* fcn_b2 = (const float*)d_in[10];

    cnn_fused<<<NB, NT>>>(x, se_w1, se_b1, se_w2, se_b2, conv_w, conv_b,
                          fcn_w1, fcn_b1, fcn_w2, fcn_b2, (float*)d_out);
}

// round 11
// speedup vs baseline: 1.5000x; 1.5000x over previous
#include <cuda_runtime.h>
#include <math.h>

// Global scratch (no cudaMalloc allowed)
__device__ float g_part[40];    // per-(block, hi) partial relu-sums: [b*2+hi]
__device__ unsigned g_done = 0; // block-arrival counter (self-resetting)

#define NB 20
#define NT 256
#define PITCH 61                // Tsh row pitch (odd -> conflict-free strided access)

__device__ __forceinline__ float fast_sigmoid(float a) {
    return 1.f / (1.f + __expf(-a));
}
__device__ __forceinline__ float fast_tanh(float a) {
    float e = __expf(2.f * a);
    return (e - 1.f) / (e + 1.f);
}
__device__ __forceinline__ void bar_sew() {   // named barrier: SE group = threads 0..127
    asm volatile("bar.sync 1, 128;" ::: "memory");
}

__global__ void __launch_bounds__(NT, 1)
cnn_fused(const float* __restrict__ x,
          const float* __restrict__ se_w1,
          const float* __restrict__ se_b1,
          const float* __restrict__ se_w2,
          const float* __restrict__ se_b2,
          const float* __restrict__ conv_w,
          const float* __restrict__ conv_b,
          const float* __restrict__ fcn_w1,
          const float* __restrict__ fcn_b1,
          const float* __restrict__ fcn_w2,
          const float* __restrict__ fcn_b2,
          float* __restrict__ out) {
    const int t = threadIdx.x;
    const int b = blockIdx.x;
    const int o = b >> 1;            // output channel 0..9
    const int q = b & 1;             // wi half: global wi in [q*60, q*60+60)
    const int lane = t & 31;
    const int wrp = t >> 5;

    __shared__ float Tsh[64 * PITCH + 64];  // T[kh][wi_local(60)], pitch 61, padded
    __shared__ float w2sh[64 * 65];         // se_w2 rows, pitch 65 (conflict-free)
    __shared__ float invn[64];
    __shared__ float scalsh[4];             // dot0a, dot0b, sumsq_wa, sumsq_wb
    __shared__ float hsh[128];
    __shared__ float ssh[128];
    __shared__ float sewsh[128];            // interleaved [kh*2 + hi]
    __shared__ float redsh[16];
    __shared__ float fw1sh[200];            // FCN tail staged in smem (pre-join)
    __shared__ float fb1sh[10];
    __shared__ float fw2sh[20];
    __shared__ float fb2sh[2];
    __shared__ float ymsh[20];
    __shared__ float h2sh[10];

    const float cb = __ldg(&conv_b[o]);

    if (t < 128) {
        // =============== SE path (warps 0-3, named barriers) ===============
        const int j = t >> 1, p = t & 1;    // GEMV1 mapping: 2 threads per row j

        // S0a: prefetch se_w1 row-half into registers + bias scalars.
        float w1r[32];
        {
            const float4* w1p = (const float4*)(se_w1 + j * 64 + p * 32);
#pragma unroll
            for (int i = 0; i < 8; i++) {
                float4 v = w1p[i];
                w1r[4 * i] = v.x; w1r[4 * i + 1] = v.y;
                w1r[4 * i + 2] = v.z; w1r[4 * i + 3] = v.w;
            }
        }
        const float b1v = __ldg(&se_b1[j]);        // for merged S2/S3
        const float b2v = __ldg(&se_b2[t & 63]);   // for S4

        // S0b: stage se_w2 row-half into pitched smem.
        {
            const float4* w2p = (const float4*)(se_w2 + j * 64 + p * 32);
            float* dst = w2sh + j * 65 + p * 32;
#pragma unroll
            for (int i = 0; i < 8; i++) {
                float4 v = w2p[i];
                dst[4 * i] = v.x; dst[4 * i + 1] = v.y;
                dst[4 * i + 2] = v.z; dst[4 * i + 3] = v.w;
            }
        }
        // S0c: stage FCN tail params into smem (rides the same DRAM trip;
        // visible to ALL warps after the join __syncthreads below).
        for (int i = t; i < 200; i += 128) fw1sh[i] = fcn_w1[i];
        if (t < 10)       fb1sh[t]      = fcn_b1[t];
        else if (t < 30)  fw2sh[t - 10] = fcn_w2[t - 10];
        else if (t < 32)  fb2sh[t - 30] = fcn_b2[t - 30];

        // S1: norms (t<64, 1 thr/channel) | wav scalars (t in [64,128), 16 thr/scalar)
        if (t < 64) {
            const float4* e = (const float4*)(x + (t + 1) * 128);
            float a0 = 0.f, a1 = 0.f, a2 = 0.f, a3 = 0.f;
#pragma unroll
            for (int i = 0; i < 32; i++) {
                float4 v = e[i];
                a0 = fmaf(v.x, v.x, a0); a1 = fmaf(v.y, v.y, a1);
                a2 = fmaf(v.z, v.z, a2); a3 = fmaf(v.w, v.w, a3);
            }
            invn[t] = rsqrtf((a0 + a1) + (a2 + a3));
        } else {
            int ts = t - 64;                // 0..63 (whole warps 2,3)
            int which = ts >> 4;            // 0: e0.wa, 1: e0.wb, 2: |wa|^2, 3: |wb|^2
            int sl = ts & 15;               // 16 threads per scalar, 8 elems each
            const float4* e0 = (const float4*)(x + 128 + sl * 8);
            const float4* wv = (const float4*)(x + ((which & 1) ? 65 * 128 : 0) + sl * 8);
            float a0 = 0.f, a1 = 0.f;
            if (which < 2) {
#pragma unroll
                for (int i = 0; i < 2; i++) {
                    float4 u = e0[i], v = wv[i];
                    a0 = fmaf(u.x, v.x, a0); a1 = fmaf(u.y, v.y, a1);
                    a0 = fmaf(u.z, v.z, a0); a1 = fmaf(u.w, v.w, a1);
                }
            } else {
#pragma unroll
                for (int i = 0; i < 2; i++) {
                    float4 v = wv[i];
                    a0 = fmaf(v.x, v.x, a0); a1 = fmaf(v.y, v.y, a1);
                    a0 = fmaf(v.z, v.z, a0); a1 = fmaf(v.w, v.w, a1);
                }
            }
            float a = a0 + a1;                       // whole warps 2,3: uniform shfls
            a += __shfl_xor_sync(0xffffffffu, a, 1);
            a += __shfl_xor_sync(0xffffffffu, a, 2);
            a += __shfl_xor_sync(0xffffffffu, a, 4);
            a += __shfl_xor_sync(0xffffffffu, a, 8);
            if (sl == 0) scalsh[which] = a;
        }
        bar_sew();

        // S2+S3 merged: u[j] = w1row . invn; then h[r][j] = tanh(c_r*u[j] + b1[j]).
        // Reference quirk: numerator = channel-0 dot only (jnp.diagonal of (64,1)),
        // so eegr[r][j] = dot0_r/(|e_j||wav_r|) and GEMV1 factorizes through u[j].
        {
            float a0 = 0.f, a1 = 0.f;
#pragma unroll
            for (int i = 0; i < 16; i++) {
                a0 = fmaf(w1r[2 * i],     invn[p * 32 + 2 * i],     a0);
                a1 = fmaf(w1r[2 * i + 1], invn[p * 32 + 2 * i + 1], a1);
            }
            float a = a0 + a1;
            a += __shfl_xor_sync(0xffffffffu, a, 1);   // whole warps 0-3
            float c0 = scalsh[0] * rsqrtf(scalsh[2]);
            float c1 = scalsh[1] * rsqrtf(scalsh[3]);
            if (p == 0) {
                hsh[j]      = fast_tanh(fmaf(c0, a, b1v));
                hsh[64 + j] = fast_tanh(fmaf(c1, a, b1v));
            }
        }
        bar_sew();

        // S4: GEMV2 + sigmoid — 1 thread per output (r,j), 64-deep dot from w2sh.
        {
            int r = t >> 6, jj = t & 63;
            const float* w = w2sh + jj * 65;
            const float* hr = hsh + r * 64;
            float a0 = 0.f, a1 = 0.f, a2 = 0.f, a3 = 0.f;
#pragma unroll
            for (int i = 0; i < 16; i++) {
                a0 = fmaf(w[4 * i],     hr[4 * i],     a0);
                a1 = fmaf(w[4 * i + 1], hr[4 * i + 1], a1);
                a2 = fmaf(w[4 * i + 2], hr[4 * i + 2], a2);
                a3 = fmaf(w[4 * i + 3], hr[4 * i + 3], a3);
            }
            ssh[t] = fast_sigmoid(((a0 + a1) + (a2 + a3)) + b2v);
        }
        bar_sew();

        // S5: row softmax over 64 (warp r -> row r), interleaved output.
        if (wrp < 2) {
            float v0 = ssh[wrp * 64 + lane];
            float v1 = ssh[wrp * 64 + 32 + lane];
            float m = fmaxf(v0, v1);
#pragma unroll
            for (int s = 16; s >= 1; s >>= 1) m = fmaxf(m, __shfl_xor_sync(0xffffffffu, m, s));
            float e0 = __expf(v0 - m), e1 = __expf(v1 - m);
            float su = e0 + e1;
#pragma unroll
            for (int s = 16; s >= 1; s >>= 1) su += __shfl_xor_sync(0xffffffffu, su, s);
            float inv = 1.f / su;
            sewsh[lane * 2 + wrp] = e0 * inv;
            sewsh[(lane + 32) * 2 + wrp] = e1 * inv;
        }
    } else {
        // =============== Stage A (warps 4-7): T tile, 30 wi per thread ===============
        int ts = t - 128;
        int row = ts >> 1, h = ts & 1;
        const float* wp = conv_w + (o * 64 + row) * 9;
        float wr[9];
#pragma unroll
        for (int i = 0; i < 9; i++) wr[i] = wp[i];
#pragma unroll
        for (int c = 0; c < 2; c++) {
            int wi0 = h * 30 + c * 15;                    // local wi base
            const float* e = x + (row + 1) * 128 + q * 60 + wi0;
            float win[23];
#pragma unroll
            for (int i = 0; i < 23; i++) win[i] = e[i];
            float* Trow = Tsh + row * PITCH + wi0;
#pragma unroll
            for (int jj = 0; jj < 15; jj++) {
                float s = 0.f;
#pragma unroll
                for (int k = 0; k < 9; k++) s = fmaf(win[jj + k], wr[k], s);
                Trow[jj] = s;
            }
        }
    }
    __syncthreads();   // join SE + stage A (also makes fcn smem staging block-visible)

    // =============== Combine: 120 outputs x 2 threads; warp-uniform shuffles ===============
    // oid = t>>1 (wi = oid>>1 local, hi = oid&1), kq = t&1, kh = kq + 2*i.
    // t >= 240: oid in [120,128) -> in-bounds garbage (Tsh padded); masked below.
    {
        int oid = t >> 1, kq = t & 1;
        int wi = oid >> 1, hi = oid & 1;
        const float* Tc = Tsh + kq * PITCH + wi;
        const float* wsp = sewsh + kq * 2 + hi;
        float p0 = 0.f, p1 = 0.f;
#pragma unroll
        for (int i = 0; i < 32; i += 2) {
            p0 = fmaf(wsp[4 * i],       Tc[2 * i * PITCH],       p0);
            p1 = fmaf(wsp[4 * (i + 1)], Tc[2 * (i + 1) * PITCH], p1);
        }
        float pp = p0 + p1;
        pp += __shfl_xor_sync(0xffffffffu, pp, 1);     // sum kq halves
        float v = 0.f;
        if (t < 240) v = fmaxf(pp + cb, 0.f);
        // Sum over wi (lane bits 2,3,4), keeping bits 0,1 fixed (bit1 = hi).
        v += __shfl_xor_sync(0xffffffffu, v, 4);
        v += __shfl_xor_sync(0xffffffffu, v, 8);
        v += __shfl_xor_sync(0xffffffffu, v, 16);
        if (lane == 0 || lane == 2) redsh[wrp * 2 + ((lane >> 1) & 1)] = v;
    }
    __syncthreads();   // the ONLY post-join block barrier

    // =============== Warp-0 end-game: gather + single block arrival + finisher ===============
    if (wrp == 0) {
        // redsh layout: [w*2 + hh], w = producing warp 0..7, hh = hi.
        float rv = (lane < 16) ? redsh[lane] : 0.f;
        // Sum over w (lane bits 1..3), keeping hh (bit 0) fixed.
        rv += __shfl_xor_sync(0xffffffffu, rv, 2);
        rv += __shfl_xor_sync(0xffffffffu, rv, 4);
        rv += __shfl_xor_sync(0xffffffffu, rv, 8);
        float s0 = __shfl_sync(0xffffffffu, rv, 0);     // hh=0 total
        float s1 = __shfl_sync(0xffffffffu, rv, 1);     // hh=1 total

        unsigned old = 0u;
        if (lane == 0) {
            g_part[b * 2 + 0] = s0;        // plain stores; ordered by the release below
            g_part[b * 2 + 1] = s1;
            asm volatile("atom.add.acq_rel.gpu.u32 %0, [%1], %2;"
                         : "=r"(old) : "l"(&g_done), "r"(1u) : "memory");
        }
        old = __shfl_sync(0xffffffffu, old, 0);         // warp-uniform broadcast

        if (old == NB - 1) {
            // Finisher: this warp saw all releases (acquire on the atomic).
            if (lane < 20) {
                int oo = lane >> 1, hh = lane & 1;
                float s = __ldcg(&g_part[(oo * 2 + 0) * 2 + hh])
                        + __ldcg(&g_part[(oo * 2 + 1) * 2 + hh]);
                ymsh[lane] = s * (1.f / 120.f);
            }
            __syncwarp();
            if (lane < 10) {
                float a = fb1sh[lane];
                const float* w = fw1sh + lane * 20;
#pragma unroll
                for (int k = 0; k < 20; k++) a = fmaf(ymsh[k], w[k], a);
                h2sh[lane] = fast_sigmoid(a);
            }
            __syncwarp();
            // All 32 lanes compute a logit redundantly (r2 = lane&1) -> uniform shfl.
            {
                int r2 = lane & 1;
                float l = fb2sh[r2];
#pragma unroll
                for (int jj = 0; jj < 10; jj++) l = fmaf(h2sh[jj], fw2sh[r2 * 10 + jj], l);
                float lo = __shfl_xor_sync(0xffffffffu, l, 1);
                if (lane == 0) {
                    float m = fmaxf(l, lo);
                    float e0 = __expf(l - m), e1 = __expf(lo - m);
                    float inv = 1.f / (e0 + e1);
                    out[0] = e0 * inv;
                    out[1] = e1 * inv;
                    g_done = 0u;           // replay-safe reset (all blocks arrived)
                }
            }
        }
    }
}

extern "C" void kernel_launch(void* const* d_in, const int* in_sizes, int n_in,
                              void* d_out, int out_size) {
    const float* x      = (const float*)d_in[0];
    const float* se_w1  = (const float*)d_in[1];
    const float* se_b1  = (const float*)d_in[2];
    const float* se_w2  = (const float*)d_in[3];
    const float* se_b2  = (const float*)d_in[4];
    const float* conv_w = (const float*)d_in[5];
    const float* conv_b = (const float*)d_in[6];
    const float* fcn_w1 = (const float*)d_in[7];
    const float* fcn_b1 = (const float*)d_in[8];
    const float* fcn_w2 = (const float*)d_in[9];
    const float* fcn_b2 = (const float*)d_in[10];

    cnn_fused<<<NB, NT>>>(x, se_w1, se_b1, se_w2, se_b2, conv_w, conv_b,
                          fcn_w1, fcn_b1, fcn_w2, fcn_b2, (float*)d_out);
}